// round 1
// baseline (speedup 1.0000x reference)
#include <cuda_runtime.h>

#define BB 16
#define C 256
#define T 1024
#define NL 4
#define NH 8
#define DH 32
#define FFD 1024
#define CTX 48
#define CHUNK 16
#define WIN 64
#define NWIN 64
#define NTOK (CTX + T)   /* 1072 */
#define EPS 1e-5f

// ---------------- scratch (device globals, no allocation) ----------------
__device__ float g_filt[BB * C * 32];
__device__ float g_act[2][(size_t)BB * NTOK * C];   // tgt_full layout, double buffered
__device__ float g_qkv[(size_t)BB * NTOK * 3 * C];
__device__ float g_attn[(size_t)BB * T * C];
__device__ float g_x1[(size_t)BB * T * C];
__device__ float g_ff[(size_t)BB * T * FFD];
__device__ float g_tmp[(size_t)BB * T * C];

// ---------------- small elementwise kernels ----------------
__global__ void filt_kernel(const float* __restrict__ emb, float* __restrict__ filt) {
    int i = blockIdx.x * 256 + threadIdx.x;
    if (i >= BB * C * 32) return;
    int rem = i % (C * 32);
    int b = i / (C * 32);
    size_t base = (size_t)b * 2 * C * 32;
    filt[i] = 0.5f * (emb[base + rem] + emb[base + C * 32 + rem]);
}

// causal depthwise conv, kernel length 32 (cross-correlation, no flip)
__global__ void conv_kernel(const float* __restrict__ x, const float* __restrict__ filt,
                            float* __restrict__ act) {
    long i = (long)blockIdx.x * 256 + threadIdx.x;
    if (i >= (long)BB * T * C) return;
    int c = i % C;
    int t = (i / C) % T;
    int b = i / ((long)C * T);
    const float* xr = x + ((long)b * C + c) * T;
    const float* f = filt + ((long)b * C + c) * 32;
    float s = 0.f;
    #pragma unroll
    for (int l = 0; l < 32; l++) {
        int ti = t + l - 31;
        if (ti >= 0) s += f[l] * xr[ti];
    }
    act[((long)b * NTOK + CTX + t) * C + c] = s;
}

// copy ctx_buf[:, layer] into first CTX rows of the activation buffer
__global__ void ctx_prefix_kernel(const float* __restrict__ ctx_in, int layer,
                                  float* __restrict__ act) {
    int i = blockIdx.x * 256 + threadIdx.x;
    if (i >= BB * CTX * C) return;
    int c = i % C;
    int j = (i / C) % CTX;
    int b = i / (C * CTX);
    act[((long)b * NTOK + j) * C + c] =
        ctx_in[(((long)b * NL + layer) * CTX + j) * C + c];
}

// ctx_buf output for this layer = last CTX tokens of layer input
__global__ void ctx_out_kernel(const float* __restrict__ act, float* __restrict__ dst,
                               int layer) {
    int i = blockIdx.x * 256 + threadIdx.x;
    if (i >= BB * CTX * C) return;
    int c = i % C;
    int j = (i / C) % CTX;
    int b = i / (C * CTX);
    dst[(((long)b * NL + layer) * CTX + j) * C + c] =
        act[((long)b * NTOK + T + j) * C + c];
}

// ---------------- GEMM: Out[M,N] = A[M,K] @ W[N,K]^T + bias, optional relu --------
template <int RELU>
__global__ __launch_bounds__(256)
void gemm_kernel(const float* __restrict__ A, const float* __restrict__ Wt,
                 const float* __restrict__ bias, float* __restrict__ Out,
                 int M, int N, int K) {
    __shared__ float As[16][68];
    __shared__ float Bs[16][68];
    const int bm = blockIdx.y * 64;
    const int bn = blockIdx.x * 64;
    const int tid = threadIdx.x;
    const int tx = tid & 15, ty = tid >> 4;
    const int lr = tid >> 2;          // 0..63 row in tile
    const int lk = (tid & 3) << 2;    // k offset 0,4,8,12
    float acc[4][4] = {};
    const float* Ag = A + (long)(bm + lr) * K + lk;
    const float* Bg = Wt + (long)(bn + lr) * K + lk;
    for (int k0 = 0; k0 < K; k0 += 16) {
        float4 a = *(const float4*)(Ag + k0);
        float4 w = *(const float4*)(Bg + k0);
        __syncthreads();
        As[lk + 0][lr] = a.x; As[lk + 1][lr] = a.y; As[lk + 2][lr] = a.z; As[lk + 3][lr] = a.w;
        Bs[lk + 0][lr] = w.x; Bs[lk + 1][lr] = w.y; Bs[lk + 2][lr] = w.z; Bs[lk + 3][lr] = w.w;
        __syncthreads();
        #pragma unroll
        for (int kk = 0; kk < 16; kk++) {
            float4 av = *(const float4*)&As[kk][ty * 4];
            float4 bv = *(const float4*)&Bs[kk][tx * 4];
            float aa[4] = {av.x, av.y, av.z, av.w};
            float bb[4] = {bv.x, bv.y, bv.z, bv.w};
            #pragma unroll
            for (int i = 0; i < 4; i++)
                #pragma unroll
                for (int j = 0; j < 4; j++) acc[i][j] += aa[i] * bb[j];
        }
    }
    #pragma unroll
    for (int i = 0; i < 4; i++) {
        int m = bm + ty * 4 + i;
        #pragma unroll
        for (int j = 0; j < 4; j++) {
            int n = bn + tx * 4 + j;
            float v = acc[i][j] + bias[n];
            if (RELU) v = fmaxf(v, 0.f);
            Out[(long)m * N + n] = v;
        }
    }
}

// ---------------- attention: per (head, window, batch) ----------------
__global__ __launch_bounds__(256)
void attn_kernel(const float* __restrict__ qkv, float* __restrict__ out) {
    const int h = blockIdx.x, w = blockIdx.y, b = blockIdx.z;
    __shared__ float qs[CHUNK][DH];
    __shared__ float ks[WIN][DH + 1];
    __shared__ float vs[WIN][DH + 1];
    __shared__ float sc[CHUNK][WIN];
    const int tid = threadIdx.x;
    const long base = (long)b * NTOK + (long)w * CHUNK;
    const int qoff = h * DH;
    for (int i = tid; i < WIN * DH; i += 256) {
        int r = i / DH, d = i % DH;
        const float* row = qkv + (base + r) * (3 * C);
        ks[r][d] = row[C + qoff + d];
        vs[r][d] = row[2 * C + qoff + d];
    }
    for (int i = tid; i < CHUNK * DH; i += 256) {
        int r = i / DH, d = i % DH;
        qs[r][d] = qkv[(base + CTX + r) * (3 * C) + qoff + d];
    }
    __syncthreads();
    const float scale = 0.17677669529663687f;  // 1/sqrt(32)
    for (int i = tid; i < CHUNK * WIN; i += 256) {
        int qi = i / WIN, j = i % WIN;
        float s = 0.f;
        #pragma unroll
        for (int d = 0; d < DH; d++) s += qs[qi][d] * ks[j][d];
        sc[qi][j] = s * scale;
    }
    __syncthreads();
    int warp = tid >> 5, lane = tid & 31;
    #pragma unroll
    for (int r = 0; r < 2; r++) {
        int qi = warp * 2 + r;
        float v0 = sc[qi][lane], v1 = sc[qi][lane + 32];
        float m = fmaxf(v0, v1);
        #pragma unroll
        for (int o = 16; o > 0; o >>= 1) m = fmaxf(m, __shfl_xor_sync(0xffffffffu, m, o));
        v0 = __expf(v0 - m);
        v1 = __expf(v1 - m);
        float s = v0 + v1;
        #pragma unroll
        for (int o = 16; o > 0; o >>= 1) s += __shfl_xor_sync(0xffffffffu, s, o);
        float inv = 1.f / s;
        sc[qi][lane] = v0 * inv;
        sc[qi][lane + 32] = v1 * inv;
    }
    __syncthreads();
    for (int i = tid; i < CHUNK * DH; i += 256) {
        int qi = i / DH, d = i % DH;
        float s = 0.f;
        #pragma unroll
        for (int j = 0; j < WIN; j++) s += sc[qi][j] * vs[j][d];
        out[((long)b * T + (long)w * CHUNK + qi) * C + qoff + d] = s;
    }
}

// ---------------- residual add + layernorm over C=256 ----------------
__global__ __launch_bounds__(256)
void add_ln_kernel(const float* __restrict__ pre, const float* __restrict__ resid,
                   long resid_bstride, const float* __restrict__ gamma,
                   const float* __restrict__ beta, float* __restrict__ out,
                   long out_bstride) {
    int t = blockIdx.x, b = blockIdx.y;
    int c = threadIdx.x;
    long prow = ((long)b * T + t) * C;
    float v = pre[prow + c] + resid[(long)b * resid_bstride + (long)t * C + c];
    __shared__ float red[256];
    red[c] = v;
    __syncthreads();
    #pragma unroll
    for (int s = 128; s > 0; s >>= 1) {
        if (c < s) red[c] += red[c + s];
        __syncthreads();
    }
    float mu = red[0] * (1.0f / C);
    __syncthreads();
    float d = v - mu;
    red[c] = d * d;
    __syncthreads();
    #pragma unroll
    for (int s = 128; s > 0; s >>= 1) {
        if (c < s) red[c] += red[c + s];
        __syncthreads();
    }
    float var = red[0] * (1.0f / C);
    float y = d * rsqrtf(var + EPS) * gamma[c] + beta[c];
    out[(long)b * out_bstride + (long)t * C + c] = y;
}

// ---------------- final transpose (B,T,C) -> (B,C,T) ----------------
__global__ void transpose_kernel(const float* __restrict__ act, float* __restrict__ out) {
    __shared__ float tile[32][33];
    int b = blockIdx.z;
    int t0 = blockIdx.x * 32, c0 = blockIdx.y * 32;
    int tx = threadIdx.x, ty = threadIdx.y;  // 32x8
    #pragma unroll
    for (int i = 0; i < 32; i += 8)
        tile[ty + i][tx] = act[((long)b * NTOK + CTX + t0 + ty + i) * C + c0 + tx];
    __syncthreads();
    #pragma unroll
    for (int i = 0; i < 32; i += 8)
        out[((long)b * C + c0 + ty + i) * T + t0 + tx] = tile[tx][ty + i];
}

// ---------------- launcher ----------------
extern "C" void kernel_launch(void* const* d_in, const int* in_sizes, int n_in,
                              void* d_out, int out_size) {
    const float* x      = (const float*)d_in[0];
    const float* emb    = (const float*)d_in[1];
    const float* ctx_in = (const float*)d_in[2];
    const float* Wqkv   = (const float*)d_in[3];
    const float* bqkv   = (const float*)d_in[4];
    const float* Wo     = (const float*)d_in[5];
    const float* bo     = (const float*)d_in[6];
    const float* W1     = (const float*)d_in[7];
    const float* b1     = (const float*)d_in[8];
    const float* W2     = (const float*)d_in[9];
    const float* b2     = (const float*)d_in[10];
    const float* ln1g   = (const float*)d_in[11];
    const float* ln1b   = (const float*)d_in[12];
    const float* ln3g   = (const float*)d_in[13];
    const float* ln3b   = (const float*)d_in[14];
    float* out = (float*)d_out;

    float *filt, *actb, *qkv, *attn, *x1, *ffb, *tmp;
    cudaGetSymbolAddress((void**)&filt, g_filt);
    cudaGetSymbolAddress((void**)&actb, g_act);
    cudaGetSymbolAddress((void**)&qkv, g_qkv);
    cudaGetSymbolAddress((void**)&attn, g_attn);
    cudaGetSymbolAddress((void**)&x1, g_x1);
    cudaGetSymbolAddress((void**)&ffb, g_ff);
    cudaGetSymbolAddress((void**)&tmp, g_tmp);

    const size_t actSz = (size_t)BB * NTOK * C;
    float* ctx_out_base = out + (size_t)BB * C * T;

    filt_kernel<<<(BB * C * 32 + 255) / 256, 256>>>(emb, filt);
    conv_kernel<<<(BB * T * C + 255) / 256, 256>>>(x, filt, actb);
    ctx_prefix_kernel<<<(BB * CTX * C + 255) / 256, 256>>>(ctx_in, 0, actb);

    for (int l = 0; l < NL; l++) {
        float* acur = actb + (size_t)(l & 1) * actSz;
        float* anxt = actb + (size_t)((l + 1) & 1) * actSz;

        ctx_out_kernel<<<(BB * CTX * C + 255) / 256, 256>>>(acur, ctx_out_base, l);

        // fused QKV over all 1072 tokens/batch
        gemm_kernel<0><<<dim3(3 * C / 64, BB * NTOK / 64), 256>>>(
            acur, Wqkv + (size_t)l * 3 * C * C, bqkv + (size_t)l * 3 * C, qkv,
            BB * NTOK, 3 * C, C);

        attn_kernel<<<dim3(NH, NWIN, BB), 256>>>(qkv, attn);

        gemm_kernel<0><<<dim3(C / 64, BB * T / 64), 256>>>(
            attn, Wo + (size_t)l * C * C, bo + (size_t)l * C, tmp, BB * T, C, C);

        add_ln_kernel<<<dim3(T, BB), 256>>>(
            tmp, acur + (size_t)CTX * C, (long)NTOK * C,
            ln1g + (size_t)l * C, ln1b + (size_t)l * C, x1, (long)T * C);

        gemm_kernel<1><<<dim3(FFD / 64, BB * T / 64), 256>>>(
            x1, W1 + (size_t)l * FFD * C, b1 + (size_t)l * FFD, ffb, BB * T, FFD, C);

        gemm_kernel<0><<<dim3(C / 64, BB * T / 64), 256>>>(
            ffb, W2 + (size_t)l * C * FFD, b2 + (size_t)l * C, tmp, BB * T, C, FFD);

        add_ln_kernel<<<dim3(T, BB), 256>>>(
            tmp, x1, (long)T * C,
            ln3g + (size_t)l * C, ln3b + (size_t)l * C,
            anxt + (size_t)CTX * C, (long)NTOK * C);

        if (l + 1 < NL)
            ctx_prefix_kernel<<<(BB * CTX * C + 255) / 256, 256>>>(ctx_in, l + 1, anxt);
    }

    // after 4 layers the output lives in buffer 0
    transpose_kernel<<<dim3(T / 32, C / 32, BB), dim3(32, 8)>>>(actb, out);
}

// round 3
// speedup vs baseline: 1.1642x; 1.1642x over previous
#include <cuda_runtime.h>

#define BB 16
#define C 256
#define T 1024
#define NL 4
#define NH 8
#define DH 32
#define FFD 1024
#define CTX 48
#define CHUNK 16
#define WIN 64
#define NWIN 64
#define NTOK (CTX + T)   /* 1072 */
#define EPS 1e-5f

// ---------------- scratch (device globals, no allocation) ----------------
__device__ float g_filt[BB * C * 32];
__device__ float g_act[2][(size_t)BB * NTOK * C];   // tgt_full layout, double buffered
__device__ float g_qkv[(size_t)BB * NTOK * 3 * C];
__device__ float g_attn[(size_t)BB * T * C];
__device__ float g_x1[(size_t)BB * T * C];
__device__ float g_ff[(size_t)BB * T * FFD];
__device__ float g_tmp[(size_t)BB * T * C];

// ---------------- small elementwise kernels ----------------
__global__ void filt_kernel(const float* __restrict__ emb, float* __restrict__ filt) {
    int i = blockIdx.x * 256 + threadIdx.x;
    if (i >= BB * C * 32) return;
    int rem = i % (C * 32);
    int b = i / (C * 32);
    size_t base = (size_t)b * 2 * C * 32;
    filt[i] = 0.5f * (emb[base + rem] + emb[base + C * 32 + rem]);
}

// causal depthwise conv, kernel length 32 (cross-correlation, no flip)
__global__ void conv_kernel(const float* __restrict__ x, const float* __restrict__ filt,
                            float* __restrict__ act) {
    long i = (long)blockIdx.x * 256 + threadIdx.x;
    if (i >= (long)BB * T * C) return;
    int c = i % C;
    int t = (i / C) % T;
    int b = i / ((long)C * T);
    const float* xr = x + ((long)b * C + c) * T;
    const float* f = filt + ((long)b * C + c) * 32;
    float s = 0.f;
    #pragma unroll
    for (int l = 0; l < 32; l++) {
        int ti = t + l - 31;
        if (ti >= 0) s += f[l] * xr[ti];
    }
    act[((long)b * NTOK + CTX + t) * C + c] = s;
}

// copy ctx_buf[:, layer] into first CTX rows of the activation buffer
__global__ void ctx_prefix_kernel(const float* __restrict__ ctx_in, int layer,
                                  float* __restrict__ act) {
    int i = blockIdx.x * 256 + threadIdx.x;
    if (i >= BB * CTX * C) return;
    int c = i % C;
    int j = (i / C) % CTX;
    int b = i / (C * CTX);
    act[((long)b * NTOK + j) * C + c] =
        ctx_in[(((long)b * NL + layer) * CTX + j) * C + c];
}

// ctx_buf output for this layer = last CTX tokens of layer input
__global__ void ctx_out_kernel(const float* __restrict__ act, float* __restrict__ dst,
                               int layer) {
    int i = blockIdx.x * 256 + threadIdx.x;
    if (i >= BB * CTX * C) return;
    int c = i % C;
    int j = (i / C) % CTX;
    int b = i / (C * CTX);
    dst[(((long)b * NL + layer) * CTX + j) * C + c] =
        act[((long)b * NTOK + T + j) * C + c];
}

// ---------------- GEMM: Out[M,N] = A[M,K] @ W[N,K]^T + bias, optional relu --------
// 128x128 tile, BK=16, 8x8 per thread, register-prefetch double buffering.
template <int RELU>
__global__ __launch_bounds__(256, 2)
void gemm_kernel(const float* __restrict__ A, const float* __restrict__ Wt,
                 const float* __restrict__ bias, float* __restrict__ Out,
                 int M, int N, int K) {
    __shared__ float As[2][16][128];
    __shared__ float Bs[2][16][128];
    const int bm = blockIdx.y * 128;
    const int bn = blockIdx.x * 128;
    const int tid = threadIdx.x;
    const int tx = tid & 15, ty = tid >> 4;
    const int lrow = tid >> 2;          // 0..63
    const int lc4  = (tid & 3) << 2;    // 0,4,8,12

    const float* Ag0 = A  + (long)(bm + lrow)       * K + lc4;
    const float* Ag1 = A  + (long)(bm + lrow + 64)  * K + lc4;
    const float* Bg0 = Wt + (long)(bn + lrow)       * K + lc4;
    const float* Bg1 = Wt + (long)(bn + lrow + 64)  * K + lc4;

    float4 a0 = *(const float4*)(Ag0);
    float4 a1 = *(const float4*)(Ag1);
    float4 b0 = *(const float4*)(Bg0);
    float4 b1 = *(const float4*)(Bg1);

    int buf = 0;
    As[0][lc4 + 0][lrow] = a0.x; As[0][lc4 + 1][lrow] = a0.y;
    As[0][lc4 + 2][lrow] = a0.z; As[0][lc4 + 3][lrow] = a0.w;
    As[0][lc4 + 0][lrow + 64] = a1.x; As[0][lc4 + 1][lrow + 64] = a1.y;
    As[0][lc4 + 2][lrow + 64] = a1.z; As[0][lc4 + 3][lrow + 64] = a1.w;
    Bs[0][lc4 + 0][lrow] = b0.x; Bs[0][lc4 + 1][lrow] = b0.y;
    Bs[0][lc4 + 2][lrow] = b0.z; Bs[0][lc4 + 3][lrow] = b0.w;
    Bs[0][lc4 + 0][lrow + 64] = b1.x; Bs[0][lc4 + 1][lrow + 64] = b1.y;
    Bs[0][lc4 + 2][lrow + 64] = b1.z; Bs[0][lc4 + 3][lrow + 64] = b1.w;
    __syncthreads();

    float acc[8][8] = {};

    for (int k0 = 16;; k0 += 16) {
        const bool last = (k0 >= K);
        if (!last) {
            a0 = *(const float4*)(Ag0 + k0);
            a1 = *(const float4*)(Ag1 + k0);
            b0 = *(const float4*)(Bg0 + k0);
            b1 = *(const float4*)(Bg1 + k0);
        }
        #pragma unroll
        for (int kk = 0; kk < 16; kk++) {
            float4 av0 = *(const float4*)&As[buf][kk][ty * 4];
            float4 av1 = *(const float4*)&As[buf][kk][ty * 4 + 64];
            float4 bv0 = *(const float4*)&Bs[buf][kk][tx * 4];
            float4 bv1 = *(const float4*)&Bs[buf][kk][tx * 4 + 64];
            float am[8] = {av0.x, av0.y, av0.z, av0.w, av1.x, av1.y, av1.z, av1.w};
            float bv[8] = {bv0.x, bv0.y, bv0.z, bv0.w, bv1.x, bv1.y, bv1.z, bv1.w};
            #pragma unroll
            for (int i = 0; i < 8; i++)
                #pragma unroll
                for (int j = 0; j < 8; j++) acc[i][j] += am[i] * bv[j];
        }
        if (last) break;
        buf ^= 1;
        As[buf][lc4 + 0][lrow] = a0.x; As[buf][lc4 + 1][lrow] = a0.y;
        As[buf][lc4 + 2][lrow] = a0.z; As[buf][lc4 + 3][lrow] = a0.w;
        As[buf][lc4 + 0][lrow + 64] = a1.x; As[buf][lc4 + 1][lrow + 64] = a1.y;
        As[buf][lc4 + 2][lrow + 64] = a1.z; As[buf][lc4 + 3][lrow + 64] = a1.w;
        Bs[buf][lc4 + 0][lrow] = b0.x; Bs[buf][lc4 + 1][lrow] = b0.y;
        Bs[buf][lc4 + 2][lrow] = b0.z; Bs[buf][lc4 + 3][lrow] = b0.w;
        Bs[buf][lc4 + 0][lrow + 64] = b1.x; Bs[buf][lc4 + 1][lrow + 64] = b1.y;
        Bs[buf][lc4 + 2][lrow + 64] = b1.z; Bs[buf][lc4 + 3][lrow + 64] = b1.w;
        __syncthreads();
    }

    #pragma unroll
    for (int im = 0; im < 2; im++) {
        #pragma unroll
        for (int i = 0; i < 4; i++) {
            const long m = bm + ty * 4 + im * 64 + i;
            #pragma unroll
            for (int jn = 0; jn < 2; jn++) {
                const int n = bn + tx * 4 + jn * 64;
                float4 v;
                v.x = acc[im * 4 + i][jn * 4 + 0] + bias[n + 0];
                v.y = acc[im * 4 + i][jn * 4 + 1] + bias[n + 1];
                v.z = acc[im * 4 + i][jn * 4 + 2] + bias[n + 2];
                v.w = acc[im * 4 + i][jn * 4 + 3] + bias[n + 3];
                if (RELU) {
                    v.x = fmaxf(v.x, 0.f); v.y = fmaxf(v.y, 0.f);
                    v.z = fmaxf(v.z, 0.f); v.w = fmaxf(v.w, 0.f);
                }
                *(float4*)(Out + m * N + n) = v;
            }
        }
    }
}

// ---------------- attention: per (head, window, batch) ----------------
__global__ __launch_bounds__(256)
void attn_kernel(const float* __restrict__ qkv, float* __restrict__ out) {
    const int h = blockIdx.x, w = blockIdx.y, b = blockIdx.z;
    __shared__ float qs[CHUNK][DH];
    __shared__ float ks[WIN][DH + 1];
    __shared__ float vs[WIN][DH + 1];
    __shared__ float sc[CHUNK][WIN];
    const int tid = threadIdx.x;
    const long base = (long)b * NTOK + (long)w * CHUNK;
    const int qoff = h * DH;
    for (int i = tid; i < WIN * DH; i += 256) {
        int r = i / DH, d = i % DH;
        const float* row = qkv + (base + r) * (3 * C);
        ks[r][d] = row[C + qoff + d];
        vs[r][d] = row[2 * C + qoff + d];
    }
    for (int i = tid; i < CHUNK * DH; i += 256) {
        int r = i / DH, d = i % DH;
        qs[r][d] = qkv[(base + CTX + r) * (3 * C) + qoff + d];
    }
    __syncthreads();
    const float scale = 0.17677669529663687f;  // 1/sqrt(32)
    for (int i = tid; i < CHUNK * WIN; i += 256) {
        int qi = i / WIN, j = i % WIN;
        float s = 0.f;
        #pragma unroll
        for (int d = 0; d < DH; d++) s += qs[qi][d] * ks[j][d];
        sc[qi][j] = s * scale;
    }
    __syncthreads();
    int warp = tid >> 5, lane = tid & 31;
    #pragma unroll
    for (int r = 0; r < 2; r++) {
        int qi = warp * 2 + r;
        float v0 = sc[qi][lane], v1 = sc[qi][lane + 32];
        float m = fmaxf(v0, v1);
        #pragma unroll
        for (int o = 16; o > 0; o >>= 1) m = fmaxf(m, __shfl_xor_sync(0xffffffffu, m, o));
        v0 = __expf(v0 - m);
        v1 = __expf(v1 - m);
        float s = v0 + v1;
        #pragma unroll
        for (int o = 16; o > 0; o >>= 1) s += __shfl_xor_sync(0xffffffffu, s, o);
        float inv = 1.f / s;
        sc[qi][lane] = v0 * inv;
        sc[qi][lane + 32] = v1 * inv;
    }
    __syncthreads();
    for (int i = tid; i < CHUNK * DH; i += 256) {
        int qi = i / DH, d = i % DH;
        float s = 0.f;
        #pragma unroll
        for (int j = 0; j < WIN; j++) s += sc[qi][j] * vs[j][d];
        out[((long)b * T + (long)w * CHUNK + qi) * C + qoff + d] = s;
    }
}

// ---------------- residual add + layernorm over C=256 ----------------
__global__ __launch_bounds__(256)
void add_ln_kernel(const float* __restrict__ pre, const float* __restrict__ resid,
                   long resid_bstride, const float* __restrict__ gamma,
                   const float* __restrict__ beta, float* __restrict__ out,
                   long out_bstride) {
    int t = blockIdx.x, b = blockIdx.y;
    int c = threadIdx.x;
    long prow = ((long)b * T + t) * C;
    float v = pre[prow + c] + resid[(long)b * resid_bstride + (long)t * C + c];
    __shared__ float red[256];
    red[c] = v;
    __syncthreads();
    #pragma unroll
    for (int s = 128; s > 0; s >>= 1) {
        if (c < s) red[c] += red[c + s];
        __syncthreads();
    }
    float mu = red[0] * (1.0f / C);
    __syncthreads();
    float d = v - mu;
    red[c] = d * d;
    __syncthreads();
    #pragma unroll
    for (int s = 128; s > 0; s >>= 1) {
        if (c < s) red[c] += red[c + s];
        __syncthreads();
    }
    float var = red[0] * (1.0f / C);
    float y = d * rsqrtf(var + EPS) * gamma[c] + beta[c];
    out[(long)b * out_bstride + (long)t * C + c] = y;
}

// ---------------- final transpose (B,T,C) -> (B,C,T) ----------------
__global__ void transpose_kernel(const float* __restrict__ act, float* __restrict__ out) {
    __shared__ float tile[32][33];
    int b = blockIdx.z;
    int t0 = blockIdx.x * 32, c0 = blockIdx.y * 32;
    int tx = threadIdx.x, ty = threadIdx.y;  // 32x8
    #pragma unroll
    for (int i = 0; i < 32; i += 8)
        tile[ty + i][tx] = act[((long)b * NTOK + CTX + t0 + ty + i) * C + c0 + tx];
    __syncthreads();
    #pragma unroll
    for (int i = 0; i < 32; i += 8)
        out[((long)b * C + c0 + ty + i) * T + t0 + tx] = tile[tx][ty + i];
}

// ---------------- launcher ----------------
extern "C" void kernel_launch(void* const* d_in, const int* in_sizes, int n_in,
                              void* d_out, int out_size) {
    const float* x      = (const float*)d_in[0];
    const float* emb    = (const float*)d_in[1];
    const float* ctx_in = (const float*)d_in[2];
    const float* Wqkv   = (const float*)d_in[3];
    const float* bqkv   = (const float*)d_in[4];
    const float* Wo     = (const float*)d_in[5];
    const float* bo     = (const float*)d_in[6];
    const float* W1     = (const float*)d_in[7];
    const float* b1     = (const float*)d_in[8];
    const float* W2     = (const float*)d_in[9];
    const float* b2     = (const float*)d_in[10];
    const float* ln1g   = (const float*)d_in[11];
    const float* ln1b   = (const float*)d_in[12];
    const float* ln3g   = (const float*)d_in[13];
    const float* ln3b   = (const float*)d_in[14];
    float* out = (float*)d_out;

    float *filt, *actb, *qkv, *attn, *x1, *ffb, *tmp;
    cudaGetSymbolAddress((void**)&filt, g_filt);
    cudaGetSymbolAddress((void**)&actb, g_act);
    cudaGetSymbolAddress((void**)&qkv, g_qkv);
    cudaGetSymbolAddress((void**)&attn, g_attn);
    cudaGetSymbolAddress((void**)&x1, g_x1);
    cudaGetSymbolAddress((void**)&ffb, g_ff);
    cudaGetSymbolAddress((void**)&tmp, g_tmp);

    const size_t actSz = (size_t)BB * NTOK * C;
    float* ctx_out_base = out + (size_t)BB * C * T;

    filt_kernel<<<(BB * C * 32 + 255) / 256, 256>>>(emb, filt);
    conv_kernel<<<(BB * T * C + 255) / 256, 256>>>(x, filt, actb);
    ctx_prefix_kernel<<<(BB * CTX * C + 255) / 256, 256>>>(ctx_in, 0, actb);

    for (int l = 0; l < NL; l++) {
        float* acur = actb + (size_t)(l & 1) * actSz;
        float* anxt = actb + (size_t)((l + 1) & 1) * actSz;

        ctx_out_kernel<<<(BB * CTX * C + 255) / 256, 256>>>(acur, ctx_out_base, l);

        // fused QKV over all 1072 tokens/batch: M=17152 (=134*128), N=768, K=256
        gemm_kernel<0><<<dim3(3 * C / 128, BB * NTOK / 128), 256>>>(
            acur, Wqkv + (size_t)l * 3 * C * C, bqkv + (size_t)l * 3 * C, qkv,
            BB * NTOK, 3 * C, C);

        attn_kernel<<<dim3(NH, NWIN, BB), 256>>>(qkv, attn);

        gemm_kernel<0><<<dim3(C / 128, BB * T / 128), 256>>>(
            attn, Wo + (size_t)l * C * C, bo + (size_t)l * C, tmp, BB * T, C, C);

        add_ln_kernel<<<dim3(T, BB), 256>>>(
            tmp, acur + (size_t)CTX * C, (long)NTOK * C,
            ln1g + (size_t)l * C, ln1b + (size_t)l * C, x1, (long)T * C);

        gemm_kernel<1><<<dim3(FFD / 128, BB * T / 128), 256>>>(
            x1, W1 + (size_t)l * FFD * C, b1 + (size_t)l * FFD, ffb, BB * T, FFD, C);

        gemm_kernel<0><<<dim3(C / 128, BB * T / 128), 256>>>(
            ffb, W2 + (size_t)l * C * FFD, b2 + (size_t)l * C, tmp, BB * T, C, FFD);

        add_ln_kernel<<<dim3(T, BB), 256>>>(
            tmp, x1, (long)T * C,
            ln3g + (size_t)l * C, ln3b + (size_t)l * C,
            anxt + (size_t)CTX * C, (long)NTOK * C);

        if (l + 1 < NL)
            ctx_prefix_kernel<<<(BB * CTX * C + 255) / 256, 256>>>(ctx_in, l + 1, anxt);
    }

    // after 4 layers the output lives in buffer 0
    transpose_kernel<<<dim3(T / 32, C / 32, BB), dim3(32, 8)>>>(actb, out);
}

// round 5
// speedup vs baseline: 1.4659x; 1.2592x over previous
#include <cuda_runtime.h>
#include <mma.h>
using namespace nvcuda;

#define BB 16
#define C 256
#define T 1024
#define NL 4
#define NH 8
#define DH 32
#define FFD 1024
#define CTX 48
#define CHUNK 16
#define WIN 64
#define NWIN 64
#define NTOK (CTX + T)   /* 1072 */
#define EPS 1e-5f

// ---------------- scratch (device globals, no allocation) ----------------
__device__ float g_filt[BB * C * 32];
__device__ float g_act[2][(size_t)BB * NTOK * C];   // tgt_full layout, double buffered
__device__ float g_qkv[(size_t)BB * NTOK * 3 * C];
__device__ float g_attn[(size_t)BB * T * C];
__device__ float g_x1[(size_t)BB * T * C];
__device__ float g_ff[(size_t)BB * T * FFD];
__device__ float g_tmp[(size_t)BB * T * C];

__device__ __forceinline__ float to_tf32(float x) {
    float r;
    asm("cvt.rna.tf32.f32 %0, %1;" : "=f"(r) : "f"(x));
    return r;
}

// ---------------- small elementwise kernels ----------------
__global__ void filt_kernel(const float* __restrict__ emb, float* __restrict__ filt) {
    int i = blockIdx.x * 256 + threadIdx.x;
    if (i >= BB * C * 32) return;
    int rem = i % (C * 32);
    int b = i / (C * 32);
    size_t base = (size_t)b * 2 * C * 32;
    filt[i] = 0.5f * (emb[base + rem] + emb[base + C * 32 + rem]);
}

// causal depthwise conv, kernel length 32 (cross-correlation, no flip)
__global__ void conv_kernel(const float* __restrict__ x, const float* __restrict__ filt,
                            float* __restrict__ act) {
    long i = (long)blockIdx.x * 256 + threadIdx.x;
    if (i >= (long)BB * T * C) return;
    int c = i % C;
    int t = (i / C) % T;
    int b = i / ((long)C * T);
    const float* xr = x + ((long)b * C + c) * T;
    const float* f = filt + ((long)b * C + c) * 32;
    float s = 0.f;
    #pragma unroll
    for (int l = 0; l < 32; l++) {
        int ti = t + l - 31;
        if (ti >= 0) s += f[l] * xr[ti];
    }
    act[((long)b * NTOK + CTX + t) * C + c] = s;
}

__global__ void ctx_prefix_kernel(const float* __restrict__ ctx_in, int layer,
                                  float* __restrict__ act) {
    int i = blockIdx.x * 256 + threadIdx.x;
    if (i >= BB * CTX * C) return;
    int c = i % C;
    int j = (i / C) % CTX;
    int b = i / (C * CTX);
    act[((long)b * NTOK + j) * C + c] =
        ctx_in[(((long)b * NL + layer) * CTX + j) * C + c];
}

__global__ void ctx_out_kernel(const float* __restrict__ act, float* __restrict__ dst,
                               int layer) {
    int i = blockIdx.x * 256 + threadIdx.x;
    if (i >= BB * CTX * C) return;
    int c = i % C;
    int j = (i / C) % CTX;
    int b = i / (C * CTX);
    dst[(((long)b * NL + layer) * CTX + j) * C + c] =
        act[((long)b * NTOK + T + j) * C + c];
}

// ---------------- tf32 tensor-core GEMM ----------------
// Out[M,N] = A[M,K] @ W[N,K]^T   (raw, no bias — consumers add bias)
// ABIAS=1: A operand is relu(A + abias[k]) applied while staging to SMEM (for FF2).
// 128x128 block tile, BK=16, 8 warps in 2(M)x4(N), warp tile 64x32.
template <int ABIAS>
__global__ __launch_bounds__(256)
void gemm_tc(const float* __restrict__ A, const float* __restrict__ Wt,
             const float* __restrict__ abias, float* __restrict__ Out,
             int M, int N, int K) {
    __shared__ float As[2][128][20];   // [m][k], row stride 20 (80B, 16B-mult)
    __shared__ float Bs[2][128][20];   // [n][k]
    const int bm = blockIdx.y * 128;
    const int bn = blockIdx.x * 128;
    const int tid = threadIdx.x;
    const int lrow = tid >> 2;          // 0..63
    const int lc4  = (tid & 3) << 2;    // 0,4,8,12
    const int wid = tid >> 5;
    const int wm = (wid & 1) * 64;      // warp M offset
    const int wn = (wid >> 1) * 32;     // warp N offset

    const float* Ag0 = A  + (long)(bm + lrow)       * K + lc4;
    const float* Ag1 = A  + (long)(bm + lrow + 64)  * K + lc4;
    const float* Bg0 = Wt + (long)(bn + lrow)       * K + lc4;
    const float* Bg1 = Wt + (long)(bn + lrow + 64)  * K + lc4;

    wmma::fragment<wmma::accumulator, 16, 16, 8, float> acc[4][2];
    #pragma unroll
    for (int i = 0; i < 4; i++)
        #pragma unroll
        for (int j = 0; j < 2; j++) wmma::fill_fragment(acc[i][j], 0.0f);

    // prologue: stage k-chunk 0
    {
        float4 a0 = *(const float4*)(Ag0);
        float4 a1 = *(const float4*)(Ag1);
        float4 b0 = *(const float4*)(Bg0);
        float4 b1 = *(const float4*)(Bg1);
        if (ABIAS) {
            float4 bi = *(const float4*)(abias + lc4);
            a0.x = fmaxf(a0.x + bi.x, 0.f); a0.y = fmaxf(a0.y + bi.y, 0.f);
            a0.z = fmaxf(a0.z + bi.z, 0.f); a0.w = fmaxf(a0.w + bi.w, 0.f);
            a1.x = fmaxf(a1.x + bi.x, 0.f); a1.y = fmaxf(a1.y + bi.y, 0.f);
            a1.z = fmaxf(a1.z + bi.z, 0.f); a1.w = fmaxf(a1.w + bi.w, 0.f);
        }
        As[0][lrow][lc4 + 0] = to_tf32(a0.x); As[0][lrow][lc4 + 1] = to_tf32(a0.y);
        As[0][lrow][lc4 + 2] = to_tf32(a0.z); As[0][lrow][lc4 + 3] = to_tf32(a0.w);
        As[0][lrow + 64][lc4 + 0] = to_tf32(a1.x); As[0][lrow + 64][lc4 + 1] = to_tf32(a1.y);
        As[0][lrow + 64][lc4 + 2] = to_tf32(a1.z); As[0][lrow + 64][lc4 + 3] = to_tf32(a1.w);
        Bs[0][lrow][lc4 + 0] = to_tf32(b0.x); Bs[0][lrow][lc4 + 1] = to_tf32(b0.y);
        Bs[0][lrow][lc4 + 2] = to_tf32(b0.z); Bs[0][lrow][lc4 + 3] = to_tf32(b0.w);
        Bs[0][lrow + 64][lc4 + 0] = to_tf32(b1.x); Bs[0][lrow + 64][lc4 + 1] = to_tf32(b1.y);
        Bs[0][lrow + 64][lc4 + 2] = to_tf32(b1.z); Bs[0][lrow + 64][lc4 + 3] = to_tf32(b1.w);
    }
    __syncthreads();

    int buf = 0;
    for (int k0 = 16;; k0 += 16) {
        const bool last = (k0 >= K);
        float4 a0, a1, b0, b1, bi;
        if (!last) {
            a0 = *(const float4*)(Ag0 + k0);
            a1 = *(const float4*)(Ag1 + k0);
            b0 = *(const float4*)(Bg0 + k0);
            b1 = *(const float4*)(Bg1 + k0);
            if (ABIAS) bi = *(const float4*)(abias + k0 + lc4);
        }

        #pragma unroll
        for (int ks = 0; ks < 16; ks += 8) {
            wmma::fragment<wmma::matrix_a, 16, 16, 8, wmma::precision::tf32, wmma::row_major> af[4];
            wmma::fragment<wmma::matrix_b, 16, 16, 8, wmma::precision::tf32, wmma::col_major> bf[2];
            #pragma unroll
            for (int i = 0; i < 4; i++)
                wmma::load_matrix_sync(af[i], &As[buf][wm + i * 16][ks], 20);
            #pragma unroll
            for (int j = 0; j < 2; j++)
                wmma::load_matrix_sync(bf[j], &Bs[buf][wn + j * 16][ks], 20);
            #pragma unroll
            for (int i = 0; i < 4; i++)
                #pragma unroll
                for (int j = 0; j < 2; j++)
                    wmma::mma_sync(acc[i][j], af[i], bf[j], acc[i][j]);
        }
        if (last) break;

        buf ^= 1;
        if (ABIAS) {
            a0.x = fmaxf(a0.x + bi.x, 0.f); a0.y = fmaxf(a0.y + bi.y, 0.f);
            a0.z = fmaxf(a0.z + bi.z, 0.f); a0.w = fmaxf(a0.w + bi.w, 0.f);
            a1.x = fmaxf(a1.x + bi.x, 0.f); a1.y = fmaxf(a1.y + bi.y, 0.f);
            a1.z = fmaxf(a1.z + bi.z, 0.f); a1.w = fmaxf(a1.w + bi.w, 0.f);
        }
        As[buf][lrow][lc4 + 0] = to_tf32(a0.x); As[buf][lrow][lc4 + 1] = to_tf32(a0.y);
        As[buf][lrow][lc4 + 2] = to_tf32(a0.z); As[buf][lrow][lc4 + 3] = to_tf32(a0.w);
        As[buf][lrow + 64][lc4 + 0] = to_tf32(a1.x); As[buf][lrow + 64][lc4 + 1] = to_tf32(a1.y);
        As[buf][lrow + 64][lc4 + 2] = to_tf32(a1.z); As[buf][lrow + 64][lc4 + 3] = to_tf32(a1.w);
        Bs[buf][lrow][lc4 + 0] = to_tf32(b0.x); Bs[buf][lrow][lc4 + 1] = to_tf32(b0.y);
        Bs[buf][lrow][lc4 + 2] = to_tf32(b0.z); Bs[buf][lrow][lc4 + 3] = to_tf32(b0.w);
        Bs[buf][lrow + 64][lc4 + 0] = to_tf32(b1.x); Bs[buf][lrow + 64][lc4 + 1] = to_tf32(b1.y);
        Bs[buf][lrow + 64][lc4 + 2] = to_tf32(b1.z); Bs[buf][lrow + 64][lc4 + 3] = to_tf32(b1.w);
        __syncthreads();
    }

    #pragma unroll
    for (int i = 0; i < 4; i++)
        #pragma unroll
        for (int j = 0; j < 2; j++)
            wmma::store_matrix_sync(Out + (long)(bm + wm + i * 16) * N + bn + wn + j * 16,
                                    acc[i][j], N, wmma::mem_row_major);
}

// ---------------- attention: per (head, window, batch); adds QKV bias ----------------
__global__ __launch_bounds__(256)
void attn_kernel(const float* __restrict__ qkv, const float* __restrict__ bqkv,
                 float* __restrict__ out) {
    const int h = blockIdx.x, w = blockIdx.y, b = blockIdx.z;
    __shared__ float qs[CHUNK][DH];
    __shared__ float ks[WIN][DH + 1];
    __shared__ float vs[WIN][DH + 1];
    __shared__ float sc[CHUNK][WIN];
    const int tid = threadIdx.x;
    const long base = (long)b * NTOK + (long)w * CHUNK;
    const int qoff = h * DH;
    for (int i = tid; i < WIN * DH; i += 256) {
        int r = i / DH, d = i % DH;
        const float* row = qkv + (base + r) * (3 * C);
        ks[r][d] = row[C + qoff + d] + bqkv[C + qoff + d];
        vs[r][d] = row[2 * C + qoff + d] + bqkv[2 * C + qoff + d];
    }
    for (int i = tid; i < CHUNK * DH; i += 256) {
        int r = i / DH, d = i % DH;
        qs[r][d] = qkv[(base + CTX + r) * (3 * C) + qoff + d] + bqkv[qoff + d];
    }
    __syncthreads();
    const float scale = 0.17677669529663687f;  // 1/sqrt(32)
    for (int i = tid; i < CHUNK * WIN; i += 256) {
        int qi = i / WIN, j = i % WIN;
        float s = 0.f;
        #pragma unroll
        for (int d = 0; d < DH; d++) s += qs[qi][d] * ks[j][d];
        sc[qi][j] = s * scale;
    }
    __syncthreads();
    int warp = tid >> 5, lane = tid & 31;
    #pragma unroll
    for (int r = 0; r < 2; r++) {
        int qi = warp * 2 + r;
        float v0 = sc[qi][lane], v1 = sc[qi][lane + 32];
        float m = fmaxf(v0, v1);
        #pragma unroll
        for (int o = 16; o > 0; o >>= 1) m = fmaxf(m, __shfl_xor_sync(0xffffffffu, m, o));
        v0 = __expf(v0 - m);
        v1 = __expf(v1 - m);
        float s = v0 + v1;
        #pragma unroll
        for (int o = 16; o > 0; o >>= 1) s += __shfl_xor_sync(0xffffffffu, s, o);
        float inv = 1.f / s;
        sc[qi][lane] = v0 * inv;
        sc[qi][lane + 32] = v1 * inv;
    }
    __syncthreads();
    for (int i = tid; i < CHUNK * DH; i += 256) {
        int qi = i / DH, d = i % DH;
        float s = 0.f;
        #pragma unroll
        for (int j = 0; j < WIN; j++) s += sc[qi][j] * vs[j][d];
        out[((long)b * T + (long)w * CHUNK + qi) * C + qoff + d] = s;
    }
}

// ---------------- (pre + pbias) + resid, then layernorm over C=256 ----------------
__global__ __launch_bounds__(256)
void add_ln_kernel(const float* __restrict__ pre, const float* __restrict__ pbias,
                   const float* __restrict__ resid, long resid_bstride,
                   const float* __restrict__ gamma, const float* __restrict__ beta,
                   float* __restrict__ out, long out_bstride) {
    int t = blockIdx.x, b = blockIdx.y;
    int c = threadIdx.x;
    long prow = ((long)b * T + t) * C;
    float v = pre[prow + c] + pbias[c] + resid[(long)b * resid_bstride + (long)t * C + c];
    __shared__ float red[256];
    red[c] = v;
    __syncthreads();
    #pragma unroll
    for (int s = 128; s > 0; s >>= 1) {
        if (c < s) red[c] += red[c + s];
        __syncthreads();
    }
    float mu = red[0] * (1.0f / C);
    __syncthreads();
    float d = v - mu;
    red[c] = d * d;
    __syncthreads();
    #pragma unroll
    for (int s = 128; s > 0; s >>= 1) {
        if (c < s) red[c] += red[c + s];
        __syncthreads();
    }
    float var = red[0] * (1.0f / C);
    float y = d * rsqrtf(var + EPS) * gamma[c] + beta[c];
    out[(long)b * out_bstride + (long)t * C + c] = y;
}

// ---------------- final transpose (B,T,C) -> (B,C,T) ----------------
__global__ void transpose_kernel(const float* __restrict__ act, float* __restrict__ out) {
    __shared__ float tile[32][33];
    int b = blockIdx.z;
    int t0 = blockIdx.x * 32, c0 = blockIdx.y * 32;
    int tx = threadIdx.x, ty = threadIdx.y;  // 32x8
    #pragma unroll
    for (int i = 0; i < 32; i += 8)
        tile[ty + i][tx] = act[((long)b * NTOK + CTX + t0 + ty + i) * C + c0 + tx];
    __syncthreads();
    #pragma unroll
    for (int i = 0; i < 32; i += 8)
        out[((long)b * C + c0 + ty + i) * T + t0 + tx] = tile[tx][ty + i];
}

// ---------------- launcher ----------------
extern "C" void kernel_launch(void* const* d_in, const int* in_sizes, int n_in,
                              void* d_out, int out_size) {
    const float* x      = (const float*)d_in[0];
    const float* emb    = (const float*)d_in[1];
    const float* ctx_in = (const float*)d_in[2];
    const float* Wqkv   = (const float*)d_in[3];
    const float* bqkv   = (const float*)d_in[4];
    const float* Wo     = (const float*)d_in[5];
    const float* bo     = (const float*)d_in[6];
    const float* W1     = (const float*)d_in[7];
    const float* b1     = (const float*)d_in[8];
    const float* W2     = (const float*)d_in[9];
    const float* b2     = (const float*)d_in[10];
    const float* ln1g   = (const float*)d_in[11];
    const float* ln1b   = (const float*)d_in[12];
    const float* ln3g   = (const float*)d_in[13];
    const float* ln3b   = (const float*)d_in[14];
    float* out = (float*)d_out;

    float *filt, *actb, *qkv, *attn, *x1, *ffb, *tmp;
    cudaGetSymbolAddress((void**)&filt, g_filt);
    cudaGetSymbolAddress((void**)&actb, g_act);
    cudaGetSymbolAddress((void**)&qkv, g_qkv);
    cudaGetSymbolAddress((void**)&attn, g_attn);
    cudaGetSymbolAddress((void**)&x1, g_x1);
    cudaGetSymbolAddress((void**)&ffb, g_ff);
    cudaGetSymbolAddress((void**)&tmp, g_tmp);

    const size_t actSz = (size_t)BB * NTOK * C;
    float* ctx_out_base = out + (size_t)BB * C * T;

    filt_kernel<<<(BB * C * 32 + 255) / 256, 256>>>(emb, filt);
    conv_kernel<<<(BB * T * C + 255) / 256, 256>>>(x, filt, actb);
    ctx_prefix_kernel<<<(BB * CTX * C + 255) / 256, 256>>>(ctx_in, 0, actb);

    for (int l = 0; l < NL; l++) {
        float* acur = actb + (size_t)(l & 1) * actSz;
        float* anxt = actb + (size_t)((l + 1) & 1) * actSz;

        ctx_out_kernel<<<(BB * CTX * C + 255) / 256, 256>>>(acur, ctx_out_base, l);

        // QKV (raw, bias added in attn): M=17152, N=768, K=256
        gemm_tc<0><<<dim3(3 * C / 128, BB * NTOK / 128), 256>>>(
            acur, Wqkv + (size_t)l * 3 * C * C, nullptr, qkv, BB * NTOK, 3 * C, C);

        attn_kernel<<<dim3(NH, NWIN, BB), 256>>>(qkv, bqkv + (size_t)l * 3 * C, attn);

        // Wo (raw, bias added in add_ln): M=16384, N=256, K=256
        gemm_tc<0><<<dim3(C / 128, BB * T / 128), 256>>>(
            attn, Wo + (size_t)l * C * C, nullptr, tmp, BB * T, C, C);

        add_ln_kernel<<<dim3(T, BB), 256>>>(
            tmp, bo + (size_t)l * C, acur + (size_t)CTX * C, (long)NTOK * C,
            ln1g + (size_t)l * C, ln1b + (size_t)l * C, x1, (long)T * C);

        // FF1 (raw; bias+relu deferred to FF2's A loader): M=16384, N=1024, K=256
        gemm_tc<0><<<dim3(FFD / 128, BB * T / 128), 256>>>(
            x1, W1 + (size_t)l * FFD * C, nullptr, ffb, BB * T, FFD, C);

        // FF2 with A := relu(ffb + b1): M=16384, N=256, K=1024
        gemm_tc<1><<<dim3(C / 128, BB * T / 128), 256>>>(
            ffb, W2 + (size_t)l * C * FFD, b1 + (size_t)l * FFD, tmp, BB * T, C, FFD);

        add_ln_kernel<<<dim3(T, BB), 256>>>(
            tmp, b2 + (size_t)l * C, x1, (long)T * C,
            ln3g + (size_t)l * C, ln3b + (size_t)l * C,
            anxt + (size_t)CTX * C, (long)NTOK * C);

        if (l + 1 < NL)
            ctx_prefix_kernel<<<(BB * CTX * C + 255) / 256, 256>>>(ctx_in, l + 1, anxt);
    }

    // after 4 layers the output lives in buffer 0
    transpose_kernel<<<dim3(T / 32, C / 32, BB), dim3(32, 8)>>>(actb, out);
}

// round 8
// speedup vs baseline: 2.0781x; 1.4176x over previous
#include <cuda_runtime.h>
#include <cstdint>
#include <mma.h>
using namespace nvcuda;

#define BB 16
#define C 256
#define T 1024
#define NL 4
#define NH 8
#define DH 32
#define FFD 1024
#define CTX 48
#define CHUNK 16
#define WIN 64
#define NWIN 64
#define NTOK (CTX + T)   /* 1072 */
#define EPS 1e-5f

// ---------------- scratch (device globals, no allocation) ----------------
__device__ float g_filt[BB * C * 32];
__device__ float g_act[2][(size_t)BB * NTOK * C];   // tgt_full layout, double buffered
__device__ float g_qkv[(size_t)BB * NTOK * 3 * C];
__device__ float g_attn[(size_t)BB * T * C];
__device__ float g_x1[(size_t)BB * T * C];
__device__ float g_ff[(size_t)BB * T * FFD];
__device__ float g_tmp[(size_t)BB * T * C];

// ---------------- cp.async helpers ----------------
__device__ __forceinline__ void cp16(unsigned dst, const float* src) {
    asm volatile("cp.async.cg.shared.global [%0], [%1], 16;" :: "r"(dst), "l"(src));
}
__device__ __forceinline__ void cp_commit() { asm volatile("cp.async.commit_group;"); }
template <int N> __device__ __forceinline__ void cp_wait() {
    asm volatile("cp.async.wait_group %0;" :: "n"(N));
}

// ---------------- small elementwise kernels ----------------
__global__ void filt_kernel(const float* __restrict__ emb, float* __restrict__ filt) {
    int i = blockIdx.x * 256 + threadIdx.x;
    if (i >= BB * C * 32) return;
    int rem = i % (C * 32);
    int b = i / (C * 32);
    size_t base = (size_t)b * 2 * C * 32;
    filt[i] = 0.5f * (emb[base + rem] + emb[base + C * 32 + rem]);
}

// causal depthwise conv, kernel length 32. t-fastest decomposition: coalesced.
__global__ void conv_kernel(const float* __restrict__ x, const float* __restrict__ filt,
                            float* __restrict__ act) {
    long i = (long)blockIdx.x * 256 + threadIdx.x;
    if (i >= (long)BB * T * C) return;
    int t = i % T;
    int c = (i / T) % C;
    int b = i / ((long)T * C);
    const float* xr = x + ((long)b * C + c) * T;
    const float* f = filt + ((long)b * C + c) * 32;
    float s = 0.f;
    #pragma unroll
    for (int l = 0; l < 32; l++) {
        int ti = t + l - 31;
        if (ti >= 0) s += f[l] * xr[ti];
    }
    act[((long)b * NTOK + CTX + t) * C + c] = s;
}

__global__ void ctx_prefix_kernel(const float* __restrict__ ctx_in, int layer,
                                  float* __restrict__ act) {
    int i = blockIdx.x * 256 + threadIdx.x;
    if (i >= BB * CTX * C) return;
    int c = i % C;
    int j = (i / C) % CTX;
    int b = i / (C * CTX);
    act[((long)b * NTOK + j) * C + c] =
        ctx_in[(((long)b * NL + layer) * CTX + j) * C + c];
}

__global__ void ctx_out_kernel(const float* __restrict__ act, float* __restrict__ dst,
                               int layer) {
    int i = blockIdx.x * 256 + threadIdx.x;
    if (i >= BB * CTX * C) return;
    int c = i % C;
    int j = (i / C) % CTX;
    int b = i / (C * CTX);
    dst[(((long)b * NL + layer) * CTX + j) * C + c] =
        act[((long)b * NTOK + T + j) * C + c];
}

// in-place relu(x + b1[k]) over g_ff, float4-vectorized (FFD/4 = 256)
__global__ void relu_bias_kernel(float4* __restrict__ ff, const float* __restrict__ b1) {
    int i = blockIdx.x * 256 + threadIdx.x;   // total BB*T*FFD/4 = 4194304
    float4 v = ff[i];
    const float4 bi = *(const float4*)(b1 + ((i & 255) << 2));
    v.x = fmaxf(v.x + bi.x, 0.f);
    v.y = fmaxf(v.y + bi.y, 0.f);
    v.z = fmaxf(v.z + bi.z, 0.f);
    v.w = fmaxf(v.w + bi.w, 0.f);
    ff[i] = v;
}

// ---------------- tf32 tensor-core GEMM, cp.async 3-stage pipeline ----------------
// Out[M,N] = A[M,K] @ W[N,K]^T  (raw; consumers handle bias)
// 128x128 block tile, BK=16, 8 warps (2M x 4N), warp tile 64x32.
// SMEM stage: A 128x16 + B 128x16 fp32, row stride 20 (pad). 3 stages = 60KB dynamic.
#define SROW 20
#define STAGE_F (128 * SROW)          /* floats per tile per stage */
__global__ __launch_bounds__(256, 2)
void gemm_tc(const float* __restrict__ A, const float* __restrict__ Wt,
             float* __restrict__ Out, int M, int N, int K) {
    extern __shared__ float smem[];
    float (*As)[128][SROW] = (float (*)[128][SROW])smem;
    float (*Bs)[128][SROW] = (float (*)[128][SROW])(smem + 3 * STAGE_F);

    const int bm = blockIdx.y * 128;
    const int bn = blockIdx.x * 128;
    const int tid = threadIdx.x;
    const int lrow = tid >> 2;          // 0..63
    const int lc4  = (tid & 3) << 2;    // 0,4,8,12
    const int wid = tid >> 5;
    const int wm = (wid & 1) * 64;
    const int wn = (wid >> 1) * 32;

    const float* Ag0 = A  + (long)(bm + lrow)      * K + lc4;
    const float* Ag1 = A  + (long)(bm + lrow + 64) * K + lc4;
    const float* Bg0 = Wt + (long)(bn + lrow)      * K + lc4;
    const float* Bg1 = Wt + (long)(bn + lrow + 64) * K + lc4;

    const unsigned sbase = (unsigned)__cvta_generic_to_shared(smem);
    const unsigned aoff0 = sbase + (unsigned)((lrow * SROW + lc4) * 4);
    const unsigned aoff1 = sbase + (unsigned)(((lrow + 64) * SROW + lc4) * 4);
    const unsigned boff0 = aoff0 + 3 * STAGE_F * 4;
    const unsigned boff1 = aoff1 + 3 * STAGE_F * 4;

    const int nk = K >> 4;

    // prologue: stages 0,1
    #pragma unroll
    for (int s = 0; s < 2; s++) {
        const unsigned so = (unsigned)(s * STAGE_F * 4);
        const int k0 = s * 16;
        cp16(aoff0 + so, Ag0 + k0);
        cp16(aoff1 + so, Ag1 + k0);
        cp16(boff0 + so, Bg0 + k0);
        cp16(boff1 + so, Bg1 + k0);
        cp_commit();
    }

    wmma::fragment<wmma::accumulator, 16, 16, 8, float> acc[4][2];
    #pragma unroll
    for (int i = 0; i < 4; i++)
        #pragma unroll
        for (int j = 0; j < 2; j++) wmma::fill_fragment(acc[i][j], 0.0f);

    for (int kt = 0; kt < nk; kt++) {
        if (kt + 2 >= nk) cp_wait<0>(); else cp_wait<1>();
        __syncthreads();
        const int buf = kt % 3;
        if (kt + 2 < nk) {
            const int sn = (kt + 2) % 3;
            const unsigned so = (unsigned)(sn * STAGE_F * 4);
            const int k0 = (kt + 2) * 16;
            cp16(aoff0 + so, Ag0 + k0);
            cp16(aoff1 + so, Ag1 + k0);
            cp16(boff0 + so, Bg0 + k0);
            cp16(boff1 + so, Bg1 + k0);
            cp_commit();
        }
        #pragma unroll
        for (int ks = 0; ks < 16; ks += 8) {
            wmma::fragment<wmma::matrix_a, 16, 16, 8, wmma::precision::tf32, wmma::row_major> af[4];
            wmma::fragment<wmma::matrix_b, 16, 16, 8, wmma::precision::tf32, wmma::col_major> bf[2];
            #pragma unroll
            for (int i = 0; i < 4; i++)
                wmma::load_matrix_sync(af[i], &As[buf][wm + i * 16][ks], SROW);
            #pragma unroll
            for (int j = 0; j < 2; j++)
                wmma::load_matrix_sync(bf[j], &Bs[buf][wn + j * 16][ks], SROW);
            #pragma unroll
            for (int i = 0; i < 4; i++)
                #pragma unroll
                for (int j = 0; j < 2; j++)
                    wmma::mma_sync(acc[i][j], af[i], bf[j], acc[i][j]);
        }
    }

    #pragma unroll
    for (int i = 0; i < 4; i++)
        #pragma unroll
        for (int j = 0; j < 2; j++)
            wmma::store_matrix_sync(Out + (long)(bm + wm + i * 16) * N + bn + wn + j * 16,
                                    acc[i][j], N, wmma::mem_row_major);
}

// ---------------- attention: per (head, window, batch); adds QKV bias ----------------
__global__ __launch_bounds__(256)
void attn_kernel(const float* __restrict__ qkv, const float* __restrict__ bqkv,
                 float* __restrict__ out) {
    const int h = blockIdx.x, w = blockIdx.y, b = blockIdx.z;
    __shared__ float qs[CHUNK][DH];
    __shared__ float ks[WIN][DH + 1];
    __shared__ float vs[WIN][DH + 1];
    __shared__ float sc[CHUNK][WIN];
    const int tid = threadIdx.x;
    const long base = (long)b * NTOK + (long)w * CHUNK;
    const int qoff = h * DH;
    for (int i = tid; i < WIN * DH; i += 256) {
        int r = i / DH, d = i % DH;
        const float* row = qkv + (base + r) * (3 * C);
        ks[r][d] = row[C + qoff + d] + bqkv[C + qoff + d];
        vs[r][d] = row[2 * C + qoff + d] + bqkv[2 * C + qoff + d];
    }
    for (int i = tid; i < CHUNK * DH; i += 256) {
        int r = i / DH, d = i % DH;
        qs[r][d] = qkv[(base + CTX + r) * (3 * C) + qoff + d] + bqkv[qoff + d];
    }
    __syncthreads();
    const float scale = 0.17677669529663687f;  // 1/sqrt(32)
    for (int i = tid; i < CHUNK * WIN; i += 256) {
        int qi = i / WIN, j = i % WIN;
        float s = 0.f;
        #pragma unroll
        for (int d = 0; d < DH; d++) s += qs[qi][d] * ks[j][d];
        sc[qi][j] = s * scale;
    }
    __syncthreads();
    int warp = tid >> 5, lane = tid & 31;
    #pragma unroll
    for (int r = 0; r < 2; r++) {
        int qi = warp * 2 + r;
        float v0 = sc[qi][lane], v1 = sc[qi][lane + 32];
        float m = fmaxf(v0, v1);
        #pragma unroll
        for (int o = 16; o > 0; o >>= 1) m = fmaxf(m, __shfl_xor_sync(0xffffffffu, m, o));
        v0 = __expf(v0 - m);
        v1 = __expf(v1 - m);
        float s = v0 + v1;
        #pragma unroll
        for (int o = 16; o > 0; o >>= 1) s += __shfl_xor_sync(0xffffffffu, s, o);
        float inv = 1.f / s;
        sc[qi][lane] = v0 * inv;
        sc[qi][lane + 32] = v1 * inv;
    }
    __syncthreads();
    for (int i = tid; i < CHUNK * DH; i += 256) {
        int qi = i / DH, d = i % DH;
        float s = 0.f;
        #pragma unroll
        for (int j = 0; j < WIN; j++) s += sc[qi][j] * vs[j][d];
        out[((long)b * T + (long)w * CHUNK + qi) * C + qoff + d] = s;
    }
}

// ---------------- (pre + pbias) + resid, then layernorm: one warp per row ----------------
__global__ __launch_bounds__(256)
void add_ln_kernel(const float* __restrict__ pre, const float* __restrict__ pbias,
                   const float* __restrict__ resid, long resid_bstride,
                   const float* __restrict__ gamma, const float* __restrict__ beta,
                   float* __restrict__ out, long out_bstride) {
    const int warp = threadIdx.x >> 5, lane = threadIdx.x & 31;
    const long row = (long)blockIdx.x * 8 + warp;   // row in [0, BB*T)
    const int t = (int)(row % T);
    const int b = (int)(row / T);
    const int c0 = lane * 8;
    const float* pr = pre + row * C + c0;
    const float* rr = resid + (long)b * resid_bstride + (long)t * C + c0;
    float v[8];
    {
        float4 p0 = *(const float4*)(pr);
        float4 p1 = *(const float4*)(pr + 4);
        float4 r0 = *(const float4*)(rr);
        float4 r1 = *(const float4*)(rr + 4);
        float4 b0 = *(const float4*)(pbias + c0);
        float4 b1 = *(const float4*)(pbias + c0 + 4);
        v[0] = p0.x + b0.x + r0.x; v[1] = p0.y + b0.y + r0.y;
        v[2] = p0.z + b0.z + r0.z; v[3] = p0.w + b0.w + r0.w;
        v[4] = p1.x + b1.x + r1.x; v[5] = p1.y + b1.y + r1.y;
        v[6] = p1.z + b1.z + r1.z; v[7] = p1.w + b1.w + r1.w;
    }
    float s1 = 0.f, s2 = 0.f;
    #pragma unroll
    for (int i = 0; i < 8; i++) { s1 += v[i]; s2 += v[i] * v[i]; }
    #pragma unroll
    for (int o = 16; o > 0; o >>= 1) {
        s1 += __shfl_xor_sync(0xffffffffu, s1, o);
        s2 += __shfl_xor_sync(0xffffffffu, s2, o);
    }
    const float mu = s1 * (1.0f / C);
    const float var = s2 * (1.0f / C) - mu * mu;
    const float inv = rsqrtf(var + EPS);
    float4 g0 = *(const float4*)(gamma + c0);
    float4 g1 = *(const float4*)(gamma + c0 + 4);
    float4 be0 = *(const float4*)(beta + c0);
    float4 be1 = *(const float4*)(beta + c0 + 4);
    float* po = out + (long)b * out_bstride + (long)t * C + c0;
    float4 o0, o1;
    o0.x = (v[0] - mu) * inv * g0.x + be0.x;
    o0.y = (v[1] - mu) * inv * g0.y + be0.y;
    o0.z = (v[2] - mu) * inv * g0.z + be0.z;
    o0.w = (v[3] - mu) * inv * g0.w + be0.w;
    o1.x = (v[4] - mu) * inv * g1.x + be1.x;
    o1.y = (v[5] - mu) * inv * g1.y + be1.y;
    o1.z = (v[6] - mu) * inv * g1.z + be1.z;
    o1.w = (v[7] - mu) * inv * g1.w + be1.w;
    *(float4*)(po) = o0;
    *(float4*)(po + 4) = o1;
}

// ---------------- final transpose (B,T,C) -> (B,C,T) ----------------
__global__ void transpose_kernel(const float* __restrict__ act, float* __restrict__ out) {
    __shared__ float tile[32][33];
    int b = blockIdx.z;
    int t0 = blockIdx.x * 32, c0 = blockIdx.y * 32;
    int tx = threadIdx.x, ty = threadIdx.y;  // 32x8
    #pragma unroll
    for (int i = 0; i < 32; i += 8)
        tile[ty + i][tx] = act[((long)b * NTOK + CTX + t0 + ty + i) * C + c0 + tx];
    __syncthreads();
    #pragma unroll
    for (int i = 0; i < 32; i += 8)
        out[((long)b * C + c0 + ty + i) * T + t0 + tx] = tile[tx][ty + i];
}

// ---------------- launcher ----------------
extern "C" void kernel_launch(void* const* d_in, const int* in_sizes, int n_in,
                              void* d_out, int out_size) {
    const float* x      = (const float*)d_in[0];
    const float* emb    = (const float*)d_in[1];
    const float* ctx_in = (const float*)d_in[2];
    const float* Wqkv   = (const float*)d_in[3];
    const float* bqkv   = (const float*)d_in[4];
    const float* Wo     = (const float*)d_in[5];
    const float* bo     = (const float*)d_in[6];
    const float* W1     = (const float*)d_in[7];
    const float* b1     = (const float*)d_in[8];
    const float* W2     = (const float*)d_in[9];
    const float* b2     = (const float*)d_in[10];
    const float* ln1g   = (const float*)d_in[11];
    const float* ln1b   = (const float*)d_in[12];
    const float* ln3g   = (const float*)d_in[13];
    const float* ln3b   = (const float*)d_in[14];
    float* out = (float*)d_out;

    float *filt, *actb, *qkv, *attn, *x1, *ffb, *tmp;
    cudaGetSymbolAddress((void**)&filt, g_filt);
    cudaGetSymbolAddress((void**)&actb, g_act);
    cudaGetSymbolAddress((void**)&qkv, g_qkv);
    cudaGetSymbolAddress((void**)&attn, g_attn);
    cudaGetSymbolAddress((void**)&x1, g_x1);
    cudaGetSymbolAddress((void**)&ffb, g_ff);
    cudaGetSymbolAddress((void**)&tmp, g_tmp);

    const int GEMM_SMEM = 3 * STAGE_F * 2 * 4;   // 61440 bytes
    cudaFuncSetAttribute(gemm_tc, cudaFuncAttributeMaxDynamicSharedMemorySize, GEMM_SMEM);

    const size_t actSz = (size_t)BB * NTOK * C;
    float* ctx_out_base = out + (size_t)BB * C * T;

    filt_kernel<<<(BB * C * 32 + 255) / 256, 256>>>(emb, filt);
    conv_kernel<<<(BB * T * C + 255) / 256, 256>>>(x, filt, actb);
    ctx_prefix_kernel<<<(BB * CTX * C + 255) / 256, 256>>>(ctx_in, 0, actb);

    for (int l = 0; l < NL; l++) {
        float* acur = actb + (size_t)(l & 1) * actSz;
        float* anxt = actb + (size_t)((l + 1) & 1) * actSz;

        ctx_out_kernel<<<(BB * CTX * C + 255) / 256, 256>>>(acur, ctx_out_base, l);

        // QKV (raw, bias added in attn): M=17152, N=768, K=256
        gemm_tc<<<dim3(3 * C / 128, BB * NTOK / 128), 256, GEMM_SMEM>>>(
            acur, Wqkv + (size_t)l * 3 * C * C, qkv, BB * NTOK, 3 * C, C);

        attn_kernel<<<dim3(NH, NWIN, BB), 256>>>(qkv, bqkv + (size_t)l * 3 * C, attn);

        // Wo (raw, bias added in add_ln): M=16384, N=256, K=256
        gemm_tc<<<dim3(C / 128, BB * T / 128), 256, GEMM_SMEM>>>(
            attn, Wo + (size_t)l * C * C, tmp, BB * T, C, C);

        add_ln_kernel<<<dim3(BB * T / 8), 256>>>(
            tmp, bo + (size_t)l * C, acur + (size_t)CTX * C, (long)NTOK * C,
            ln1g + (size_t)l * C, ln1b + (size_t)l * C, x1, (long)T * C);

        // FF1 (raw): M=16384, N=1024, K=256
        gemm_tc<<<dim3(FFD / 128, BB * T / 128), 256, GEMM_SMEM>>>(
            x1, W1 + (size_t)l * FFD * C, ffb, BB * T, FFD, C);

        // relu(ffb + b1) in place
        relu_bias_kernel<<<(BB * T * FFD / 4) / 256, 256>>>((float4*)ffb, b1 + (size_t)l * FFD);

        // FF2: M=16384, N=256, K=1024
        gemm_tc<<<dim3(C / 128, BB * T / 128), 256, GEMM_SMEM>>>(
            ffb, W2 + (size_t)l * C * FFD, tmp, BB * T, C, FFD);

        add_ln_kernel<<<dim3(BB * T / 8), 256>>>(
            tmp, b2 + (size_t)l * C, x1, (long)T * C,
            ln3g + (size_t)l * C, ln3b + (size_t)l * C,
            anxt + (size_t)CTX * C, (long)NTOK * C);

        if (l + 1 < NL)
            ctx_prefix_kernel<<<(BB * CTX * C + 255) / 256, 256>>>(ctx_in, l + 1, anxt);
    }

    // after 4 layers the output lives in buffer 0
    transpose_kernel<<<dim3(T / 32, C / 32, BB), dim3(32, 8)>>>(actb, out);
}

// round 9
// speedup vs baseline: 2.2988x; 1.1062x over previous
#include <cuda_runtime.h>
#include <cstdint>
#include <mma.h>
using namespace nvcuda;

#define BB 16
#define C 256
#define T 1024
#define NL 4
#define NH 8
#define DH 32
#define FFD 1024
#define CTX 48
#define CHUNK 16
#define WIN 64
#define NWIN 64
#define NTOK (CTX + T)   /* 1072 */
#define EPS 1e-5f

// ---------------- scratch (device globals, no allocation) ----------------
__device__ float g_filt[BB * C * 32];
__device__ float g_act[2][(size_t)BB * NTOK * C];   // tgt_full layout, double buffered
__device__ float g_qkv[(size_t)BB * NTOK * 3 * C];
__device__ float g_attn[(size_t)BB * T * C];
__device__ float g_x1[(size_t)BB * T * C];
__device__ float g_ff[(size_t)BB * T * FFD];
__device__ float g_tmp[(size_t)BB * T * C];
__device__ float g_btile[NL * 16 * FFD];            // 16-row broadcast of b1 per layer

// ---------------- cp.async helpers ----------------
__device__ __forceinline__ void cp16(unsigned dst, const float* src) {
    asm volatile("cp.async.cg.shared.global [%0], [%1], 16;" :: "r"(dst), "l"(src));
}
__device__ __forceinline__ void cp_commit() { asm volatile("cp.async.commit_group;"); }
template <int N> __device__ __forceinline__ void cp_wait() {
    asm volatile("cp.async.wait_group %0;" :: "n"(N));
}

// ---------------- small elementwise kernels ----------------
__global__ void filt_kernel(const float* __restrict__ emb, float* __restrict__ filt) {
    int i = blockIdx.x * 256 + threadIdx.x;
    if (i >= BB * C * 32) return;
    int rem = i % (C * 32);
    int b = i / (C * 32);
    size_t base = (size_t)b * 2 * C * 32;
    filt[i] = 0.5f * (emb[base + rem] + emb[base + C * 32 + rem]);
}

// broadcast b1[l][k] into 16 rows per layer (for GEMM accumulator init)
__global__ void btile_kernel(const float* __restrict__ b1, float* __restrict__ btile) {
    int i = blockIdx.x * 256 + threadIdx.x;   // NL*16*FFD = 65536
    int k = i % FFD;
    int l = i / (16 * FFD);
    btile[i] = b1[l * FFD + k];
}

// causal depthwise conv, kernel length 32. t-fastest decomposition: coalesced.
__global__ void conv_kernel(const float* __restrict__ x, const float* __restrict__ filt,
                            float* __restrict__ act) {
    long i = (long)blockIdx.x * 256 + threadIdx.x;
    if (i >= (long)BB * T * C) return;
    int t = i % T;
    int c = (i / T) % C;
    int b = i / ((long)T * C);
    const float* xr = x + ((long)b * C + c) * T;
    const float* f = filt + ((long)b * C + c) * 32;
    float s = 0.f;
    #pragma unroll
    for (int l = 0; l < 32; l++) {
        int ti = t + l - 31;
        if (ti >= 0) s += f[l] * xr[ti];
    }
    act[((long)b * NTOK + CTX + t) * C + c] = s;
}

__global__ void ctx_prefix_kernel(const float* __restrict__ ctx_in, int layer,
                                  float* __restrict__ act) {
    int i = blockIdx.x * 256 + threadIdx.x;
    if (i >= BB * CTX * C) return;
    int c = i % C;
    int j = (i / C) % CTX;
    int b = i / (C * CTX);
    act[((long)b * NTOK + j) * C + c] =
        ctx_in[(((long)b * NL + layer) * CTX + j) * C + c];
}

__global__ void ctx_out_kernel(const float* __restrict__ act, float* __restrict__ dst,
                               int layer) {
    int i = blockIdx.x * 256 + threadIdx.x;
    if (i >= BB * CTX * C) return;
    int c = i % C;
    int j = (i / C) % CTX;
    int b = i / (C * CTX);
    dst[(((long)b * NL + layer) * CTX + j) * C + c] =
        act[((long)b * NTOK + T + j) * C + c];
}

// ---------------- tf32 tensor-core GEMM, cp.async 3-stage pipeline ----------------
// Out[M,N] = A[M,K] @ W[N,K]^T  (+ optional acc-init from 16-row bias tile, + optional relu)
// 128x128 block tile, BK=16, 4 warps (2M x 2N), warp tile 64x64, 128 threads.
#define SROW 20
#define STAGE_F (128 * SROW)          /* floats per tile per stage */
template <int LDACC, int RELU>
__global__ __launch_bounds__(128, 2)
void gemm_tc(const float* __restrict__ A, const float* __restrict__ Wt,
             const float* __restrict__ accinit, float* __restrict__ Out,
             int M, int N, int K) {
    extern __shared__ float smem[];
    float (*As)[128][SROW] = (float (*)[128][SROW])smem;
    float (*Bs)[128][SROW] = (float (*)[128][SROW])(smem + 3 * STAGE_F);

    const int bm = blockIdx.y * 128;
    const int bn = blockIdx.x * 128;
    const int tid = threadIdx.x;
    const int lrow = tid >> 2;          // 0..31
    const int lc4  = (tid & 3) << 2;    // 0,4,8,12
    const int wid = tid >> 5;           // 0..3
    const int wm = (wid & 1) * 64;
    const int wn = (wid >> 1) * 64;

    const float* Ag[4];
    const float* Bg[4];
    #pragma unroll
    for (int r = 0; r < 4; r++) {
        Ag[r] = A  + (long)(bm + lrow + r * 32) * K + lc4;
        Bg[r] = Wt + (long)(bn + lrow + r * 32) * K + lc4;
    }

    const unsigned sbase = (unsigned)__cvta_generic_to_shared(smem);
    unsigned aoff[4], boff[4];
    #pragma unroll
    for (int r = 0; r < 4; r++) {
        aoff[r] = sbase + (unsigned)(((lrow + r * 32) * SROW + lc4) * 4);
        boff[r] = aoff[r] + 3 * STAGE_F * 4;
    }

    const int nk = K >> 4;

    // prologue: stages 0,1
    #pragma unroll
    for (int s = 0; s < 2; s++) {
        const unsigned so = (unsigned)(s * STAGE_F * 4);
        const int k0 = s * 16;
        #pragma unroll
        for (int r = 0; r < 4; r++) {
            cp16(aoff[r] + so, Ag[r] + k0);
            cp16(boff[r] + so, Bg[r] + k0);
        }
        cp_commit();
    }

    wmma::fragment<wmma::accumulator, 16, 16, 8, float> acc[4][4];
    if (LDACC) {
        #pragma unroll
        for (int i = 0; i < 4; i++)
            #pragma unroll
            for (int j = 0; j < 4; j++)
                wmma::load_matrix_sync(acc[i][j], accinit + bn + wn + j * 16, N,
                                       wmma::mem_row_major);
    } else {
        #pragma unroll
        for (int i = 0; i < 4; i++)
            #pragma unroll
            for (int j = 0; j < 4; j++) wmma::fill_fragment(acc[i][j], 0.0f);
    }

    for (int kt = 0; kt < nk; kt++) {
        if (kt + 2 >= nk) cp_wait<0>(); else cp_wait<1>();
        __syncthreads();
        const int buf = kt % 3;
        if (kt + 2 < nk) {
            const int sn = (kt + 2) % 3;
            const unsigned so = (unsigned)(sn * STAGE_F * 4);
            const int k0 = (kt + 2) * 16;
            #pragma unroll
            for (int r = 0; r < 4; r++) {
                cp16(aoff[r] + so, Ag[r] + k0);
                cp16(boff[r] + so, Bg[r] + k0);
            }
            cp_commit();
        }
        #pragma unroll
        for (int ks = 0; ks < 16; ks += 8) {
            wmma::fragment<wmma::matrix_a, 16, 16, 8, wmma::precision::tf32, wmma::row_major> af[4];
            wmma::fragment<wmma::matrix_b, 16, 16, 8, wmma::precision::tf32, wmma::col_major> bf[4];
            #pragma unroll
            for (int i = 0; i < 4; i++)
                wmma::load_matrix_sync(af[i], &As[buf][wm + i * 16][ks], SROW);
            #pragma unroll
            for (int j = 0; j < 4; j++)
                wmma::load_matrix_sync(bf[j], &Bs[buf][wn + j * 16][ks], SROW);
            #pragma unroll
            for (int i = 0; i < 4; i++)
                #pragma unroll
                for (int j = 0; j < 4; j++)
                    wmma::mma_sync(acc[i][j], af[i], bf[j], acc[i][j]);
        }
    }

    #pragma unroll
    for (int i = 0; i < 4; i++)
        #pragma unroll
        for (int j = 0; j < 4; j++) {
            if (RELU) {
                #pragma unroll
                for (int t = 0; t < acc[i][j].num_elements; t++)
                    acc[i][j].x[t] = fmaxf(acc[i][j].x[t], 0.0f);
            }
            wmma::store_matrix_sync(Out + (long)(bm + wm + i * 16) * N + bn + wn + j * 16,
                                    acc[i][j], N, wmma::mem_row_major);
        }
}

// ---------------- attention: per (head, window, batch); adds QKV bias ----------------
__global__ __launch_bounds__(256)
void attn_kernel(const float* __restrict__ qkv, const float* __restrict__ bqkv,
                 float* __restrict__ out) {
    const int h = blockIdx.x, w = blockIdx.y, b = blockIdx.z;
    __shared__ float qs[CHUNK][DH];
    __shared__ float ks[WIN][DH + 1];
    __shared__ float vs[WIN][DH + 1];
    __shared__ float sc[CHUNK][WIN];
    const int tid = threadIdx.x;
    const long base = (long)b * NTOK + (long)w * CHUNK;
    const int qoff = h * DH;
    for (int i = tid; i < WIN * DH; i += 256) {
        int r = i / DH, d = i % DH;
        const float* row = qkv + (base + r) * (3 * C);
        ks[r][d] = row[C + qoff + d] + bqkv[C + qoff + d];
        vs[r][d] = row[2 * C + qoff + d] + bqkv[2 * C + qoff + d];
    }
    for (int i = tid; i < CHUNK * DH; i += 256) {
        int r = i / DH, d = i % DH;
        qs[r][d] = qkv[(base + CTX + r) * (3 * C) + qoff + d] + bqkv[qoff + d];
    }
    __syncthreads();
    const float scale = 0.17677669529663687f;  // 1/sqrt(32)
    for (int i = tid; i < CHUNK * WIN; i += 256) {
        int qi = i / WIN, j = i % WIN;
        float s = 0.f;
        #pragma unroll
        for (int d = 0; d < DH; d++) s += qs[qi][d] * ks[j][d];
        sc[qi][j] = s * scale;
    }
    __syncthreads();
    int warp = tid >> 5, lane = tid & 31;
    #pragma unroll
    for (int r = 0; r < 2; r++) {
        int qi = warp * 2 + r;
        float v0 = sc[qi][lane], v1 = sc[qi][lane + 32];
        float m = fmaxf(v0, v1);
        #pragma unroll
        for (int o = 16; o > 0; o >>= 1) m = fmaxf(m, __shfl_xor_sync(0xffffffffu, m, o));
        v0 = __expf(v0 - m);
        v1 = __expf(v1 - m);
        float s = v0 + v1;
        #pragma unroll
        for (int o = 16; o > 0; o >>= 1) s += __shfl_xor_sync(0xffffffffu, s, o);
        float inv = 1.f / s;
        sc[qi][lane] = v0 * inv;
        sc[qi][lane + 32] = v1 * inv;
    }
    __syncthreads();
    for (int i = tid; i < CHUNK * DH; i += 256) {
        int qi = i / DH, d = i % DH;
        float s = 0.f;
        #pragma unroll
        for (int j = 0; j < WIN; j++) s += sc[qi][j] * vs[j][d];
        out[((long)b * T + (long)w * CHUNK + qi) * C + qoff + d] = s;
    }
}

// ---------------- (pre + pbias) + resid, then layernorm: one warp per row ----------------
__global__ __launch_bounds__(256)
void add_ln_kernel(const float* __restrict__ pre, const float* __restrict__ pbias,
                   const float* __restrict__ resid, long resid_bstride,
                   const float* __restrict__ gamma, const float* __restrict__ beta,
                   float* __restrict__ out, long out_bstride) {
    const int warp = threadIdx.x >> 5, lane = threadIdx.x & 31;
    const long row = (long)blockIdx.x * 8 + warp;   // row in [0, BB*T)
    const int t = (int)(row % T);
    const int b = (int)(row / T);
    const int c0 = lane * 8;
    const float* pr = pre + row * C + c0;
    const float* rr = resid + (long)b * resid_bstride + (long)t * C + c0;
    float v[8];
    {
        float4 p0 = *(const float4*)(pr);
        float4 p1 = *(const float4*)(pr + 4);
        float4 r0 = *(const float4*)(rr);
        float4 r1 = *(const float4*)(rr + 4);
        float4 b0 = *(const float4*)(pbias + c0);
        float4 b1 = *(const float4*)(pbias + c0 + 4);
        v[0] = p0.x + b0.x + r0.x; v[1] = p0.y + b0.y + r0.y;
        v[2] = p0.z + b0.z + r0.z; v[3] = p0.w + b0.w + r0.w;
        v[4] = p1.x + b1.x + r1.x; v[5] = p1.y + b1.y + r1.y;
        v[6] = p1.z + b1.z + r1.z; v[7] = p1.w + b1.w + r1.w;
    }
    float s1 = 0.f, s2 = 0.f;
    #pragma unroll
    for (int i = 0; i < 8; i++) { s1 += v[i]; s2 += v[i] * v[i]; }
    #pragma unroll
    for (int o = 16; o > 0; o >>= 1) {
        s1 += __shfl_xor_sync(0xffffffffu, s1, o);
        s2 += __shfl_xor_sync(0xffffffffu, s2, o);
    }
    const float mu = s1 * (1.0f / C);
    const float var = s2 * (1.0f / C) - mu * mu;
    const float inv = rsqrtf(var + EPS);
    float4 g0 = *(const float4*)(gamma + c0);
    float4 g1 = *(const float4*)(gamma + c0 + 4);
    float4 be0 = *(const float4*)(beta + c0);
    float4 be1 = *(const float4*)(beta + c0 + 4);
    float* po = out + (long)b * out_bstride + (long)t * C + c0;
    float4 o0, o1;
    o0.x = (v[0] - mu) * inv * g0.x + be0.x;
    o0.y = (v[1] - mu) * inv * g0.y + be0.y;
    o0.z = (v[2] - mu) * inv * g0.z + be0.z;
    o0.w = (v[3] - mu) * inv * g0.w + be0.w;
    o1.x = (v[4] - mu) * inv * g1.x + be1.x;
    o1.y = (v[5] - mu) * inv * g1.y + be1.y;
    o1.z = (v[6] - mu) * inv * g1.z + be1.z;
    o1.w = (v[7] - mu) * inv * g1.w + be1.w;
    *(float4*)(po) = o0;
    *(float4*)(po + 4) = o1;
}

// ---------------- final transpose (B,T,C) -> (B,C,T) ----------------
__global__ void transpose_kernel(const float* __restrict__ act, float* __restrict__ out) {
    __shared__ float tile[32][33];
    int b = blockIdx.z;
    int t0 = blockIdx.x * 32, c0 = blockIdx.y * 32;
    int tx = threadIdx.x, ty = threadIdx.y;  // 32x8
    #pragma unroll
    for (int i = 0; i < 32; i += 8)
        tile[ty + i][tx] = act[((long)b * NTOK + CTX + t0 + ty + i) * C + c0 + tx];
    __syncthreads();
    #pragma unroll
    for (int i = 0; i < 32; i += 8)
        out[((long)b * C + c0 + ty + i) * T + t0 + tx] = tile[tx][ty + i];
}

// ---------------- launcher ----------------
extern "C" void kernel_launch(void* const* d_in, const int* in_sizes, int n_in,
                              void* d_out, int out_size) {
    const float* x      = (const float*)d_in[0];
    const float* emb    = (const float*)d_in[1];
    const float* ctx_in = (const float*)d_in[2];
    const float* Wqkv   = (const float*)d_in[3];
    const float* bqkv   = (const float*)d_in[4];
    const float* Wo     = (const float*)d_in[5];
    const float* bo     = (const float*)d_in[6];
    const float* W1     = (const float*)d_in[7];
    const float* b1     = (const float*)d_in[8];
    const float* W2     = (const float*)d_in[9];
    const float* b2     = (const float*)d_in[10];
    const float* ln1g   = (const float*)d_in[11];
    const float* ln1b   = (const float*)d_in[12];
    const float* ln3g   = (const float*)d_in[13];
    const float* ln3b   = (const float*)d_in[14];
    float* out = (float*)d_out;

    float *filt, *actb, *qkv, *attn, *x1, *ffb, *tmp, *btile;
    cudaGetSymbolAddress((void**)&filt, g_filt);
    cudaGetSymbolAddress((void**)&actb, g_act);
    cudaGetSymbolAddress((void**)&qkv, g_qkv);
    cudaGetSymbolAddress((void**)&attn, g_attn);
    cudaGetSymbolAddress((void**)&x1, g_x1);
    cudaGetSymbolAddress((void**)&ffb, g_ff);
    cudaGetSymbolAddress((void**)&tmp, g_tmp);
    cudaGetSymbolAddress((void**)&btile, g_btile);

    const int GEMM_SMEM = 3 * STAGE_F * 2 * 4;   // 61440 bytes
    cudaFuncSetAttribute(gemm_tc<0, 0>, cudaFuncAttributeMaxDynamicSharedMemorySize, GEMM_SMEM);
    cudaFuncSetAttribute(gemm_tc<1, 1>, cudaFuncAttributeMaxDynamicSharedMemorySize, GEMM_SMEM);

    const size_t actSz = (size_t)BB * NTOK * C;
    float* ctx_out_base = out + (size_t)BB * C * T;

    filt_kernel<<<(BB * C * 32 + 255) / 256, 256>>>(emb, filt);
    btile_kernel<<<(NL * 16 * FFD) / 256, 256>>>(b1, btile);
    conv_kernel<<<(BB * T * C + 255) / 256, 256>>>(x, filt, actb);
    ctx_prefix_kernel<<<(BB * CTX * C + 255) / 256, 256>>>(ctx_in, 0, actb);

    for (int l = 0; l < NL; l++) {
        float* acur = actb + (size_t)(l & 1) * actSz;
        float* anxt = actb + (size_t)((l + 1) & 1) * actSz;

        // QKV (raw, bias added in attn): M=17152, N=768, K=256
        gemm_tc<0, 0><<<dim3(3 * C / 128, BB * NTOK / 128), 128, GEMM_SMEM>>>(
            acur, Wqkv + (size_t)l * 3 * C * C, nullptr, qkv, BB * NTOK, 3 * C, C);

        ctx_out_kernel<<<(BB * CTX * C + 255) / 256, 256>>>(acur, ctx_out_base, l);

        attn_kernel<<<dim3(NH, NWIN, BB), 256>>>(qkv, bqkv + (size_t)l * 3 * C, attn);

        // Wo (raw, bias added in add_ln): M=16384, N=256, K=256
        gemm_tc<0, 0><<<dim3(C / 128, BB * T / 128), 128, GEMM_SMEM>>>(
            attn, Wo + (size_t)l * C * C, nullptr, tmp, BB * T, C, C);

        add_ln_kernel<<<dim3(BB * T / 8), 256>>>(
            tmp, bo + (size_t)l * C, acur + (size_t)CTX * C, (long)NTOK * C,
            ln1g + (size_t)l * C, ln1b + (size_t)l * C, x1, (long)T * C);

        // FF1 fused: acc init = b1 broadcast tile, relu in epilogue. M=16384, N=1024, K=256
        gemm_tc<1, 1><<<dim3(FFD / 128, BB * T / 128), 128, GEMM_SMEM>>>(
            x1, W1 + (size_t)l * FFD * C, btile + (size_t)l * 16 * FFD, ffb,
            BB * T, FFD, C);

        // FF2: M=16384, N=256, K=1024
        gemm_tc<0, 0><<<dim3(C / 128, BB * T / 128), 128, GEMM_SMEM>>>(
            ffb, W2 + (size_t)l * C * FFD, nullptr, tmp, BB * T, C, FFD);

        add_ln_kernel<<<dim3(BB * T / 8), 256>>>(
            tmp, b2 + (size_t)l * C, x1, (long)T * C,
            ln3g + (size_t)l * C, ln3b + (size_t)l * C,
            anxt + (size_t)CTX * C, (long)NTOK * C);

        if (l + 1 < NL)
            ctx_prefix_kernel<<<(BB * CTX * C + 255) / 256, 256>>>(ctx_in, l + 1, anxt);
    }

    // after 4 layers the output lives in buffer 0
    transpose_kernel<<<dim3(T / 32, C / 32, BB), dim3(32, 8)>>>(actb, out);
}